// round 4
// baseline (speedup 1.0000x reference)
#include <cuda_runtime.h>
#include <math.h>

#define Bz   128
#define Tz   1024
#define INz  256
#define Hz   512
#define H2z  1024
#define H4z  2048
#define OUTz 128
#define EPSz 1e-5f
#define NB   128   // persistent CTAs in scan kernel
#define NT   128   // threads per scan CTA

// ---------------- device scratch (static allocation only) ----------------
__device__ float g_P0[(size_t)Tz * 2 * Bz * Hz];     // [t][dir][b][n], biases folded
__device__ float g_WTih0[2 * INz * Hz];              // [dir][k][n]
__device__ float g_WThh0[2 * Hz * Hz];
__device__ float g_WTih1[2 * H2z * Hz];
__device__ float g_WThh1[2 * Hz * Hz];
__device__ float g_WTfc1[H2z * H4z];                 // [k][n] n=2048
__device__ float g_WTfc2[H4z * OUTz];                // [k][o]
__device__ float g_h[2][4][Bz * Hz];                 // ping-pong states: slots 0,1=L0 f/b; 2,3=L1 f/b
__device__ float g_bn1[Bz * H2z];
__device__ float g_fc1[Bz * H4z];
__device__ float g_bn2[Bz * H4z];
__device__ unsigned g_bar_arrive;
__device__ volatile unsigned g_bar_gen;

// ---------------- generic transpose: out[(d*C+c)*R+r] = in[(d*R+r)*C+c] ----------------
__global__ void k_tr(const float* __restrict__ in, float* __restrict__ out, int D, int R, int C) {
    long total = (long)D * R * C;
    long idx = (long)blockIdx.x * 256 + threadIdx.x;
    if (idx >= total) return;
    int r = (int)(idx % R);
    long q = idx / R;
    int c = (int)(q % C);
    int d = (int)(q / C);
    out[idx] = in[((long)d * R + r) * C + c];
}

__global__ void k_init_h(const float* __restrict__ h0) {
    int idx = blockIdx.x * 256 + threadIdx.x;
    if (idx < 4 * Bz * Hz) (&g_h[1][0][0])[idx] = h0[idx];
}

// ---------------- Phase A: P0[t][dir][b][n] = x_t @ Wih0^T + b_ih0 + b_hh0 ----------------
// rows r = b*T + t (x is [B][T][IN] row-major => A[r][k] = x[r*IN+k])
// BM=64 BN=64 BK=16, 256 threads, TM=TN=4
__global__ void k_phase_a(const float* __restrict__ x,
                          const float* __restrict__ bih,
                          const float* __restrict__ bhh) {
    __shared__ float sA[64 * 17];
    __shared__ float sB[16 * 64];
    const int tid = threadIdx.x;
    const int r0  = blockIdx.x * 64;
    const int n0  = blockIdx.y * 64;
    const int dir = blockIdx.z;
    const int ty = tid >> 4, tx = tid & 15;
    float acc[4][4] = {};
    const float* Wt = g_WTih0 + (size_t)dir * INz * Hz;

    for (int kc = 0; kc < INz; kc += 16) {
        __syncthreads();
        {
            int m = tid >> 2, kq = tid & 3;
            float4 v = __ldg(reinterpret_cast<const float4*>(x + (size_t)(r0 + m) * INz + kc + kq * 4));
            sA[m * 17 + kq * 4 + 0] = v.x;
            sA[m * 17 + kq * 4 + 1] = v.y;
            sA[m * 17 + kq * 4 + 2] = v.z;
            sA[m * 17 + kq * 4 + 3] = v.w;
        }
        {
            int k = tid >> 4, nq = tid & 15;
            float4 v = __ldg(reinterpret_cast<const float4*>(Wt + (size_t)(kc + k) * Hz + n0 + nq * 4));
            *reinterpret_cast<float4*>(sB + k * 64 + nq * 4) = v;
        }
        __syncthreads();
#pragma unroll
        for (int kk = 0; kk < 16; kk++) {
            float a0 = sA[(ty * 4 + 0) * 17 + kk];
            float a1 = sA[(ty * 4 + 1) * 17 + kk];
            float a2 = sA[(ty * 4 + 2) * 17 + kk];
            float a3 = sA[(ty * 4 + 3) * 17 + kk];
            float4 b = *reinterpret_cast<float4*>(sB + kk * 64 + tx * 4);
            acc[0][0] += a0 * b.x; acc[0][1] += a0 * b.y; acc[0][2] += a0 * b.z; acc[0][3] += a0 * b.w;
            acc[1][0] += a1 * b.x; acc[1][1] += a1 * b.y; acc[1][2] += a1 * b.z; acc[1][3] += a1 * b.w;
            acc[2][0] += a2 * b.x; acc[2][1] += a2 * b.y; acc[2][2] += a2 * b.z; acc[2][3] += a2 * b.w;
            acc[3][0] += a3 * b.x; acc[3][1] += a3 * b.y; acc[3][2] += a3 * b.z; acc[3][3] += a3 * b.w;
        }
    }
    int n = n0 + tx * 4;
    float4 bi = __ldg(reinterpret_cast<const float4*>(bih + dir * Hz + n));
    float4 bh = __ldg(reinterpret_cast<const float4*>(bhh + dir * Hz + n));
#pragma unroll
    for (int i = 0; i < 4; i++) {
        int r = r0 + ty * 4 + i;
        int t = r & (Tz - 1);
        int b_ = r >> 10;
        float4 o;
        o.x = acc[i][0] + bi.x + bh.x;
        o.y = acc[i][1] + bi.y + bh.y;
        o.z = acc[i][2] + bi.z + bh.z;
        o.w = acc[i][3] + bi.w + bh.w;
        *reinterpret_cast<float4*>(g_P0 + (((size_t)t * 2 + dir) * Bz + b_) * Hz + n) = o;
    }
}

// ---------------- scan-phase GEMM core: C[64x32] += A[m0..m0+63][0..511] * Wt ----------------
// A: [128][512] row-major; Wt: [512][512] row-major ([k][n]); BK=32, 16 chunks.
// Register-staged double-buffered pipeline: LDG for chunk c+1 issues before
// computing chunk c; one __syncthreads per chunk.
__device__ __forceinline__ void gemm512_acc(const float* __restrict__ A,
                                            const float* __restrict__ Wt,
                                            int m0, int n0, int tid,
                                            float (*sA)[64 * 33], float (*sB)[32 * 32],
                                            float acc[4][4]) {
    const int ty = tid >> 3, tx = tid & 7;
    const int lm  = tid >> 3;          // A-load row base within 64 (fid>>3, u adds 16)
    const int lkq = tid & 7;           // A-load k-quad
    const int lk  = tid >> 3;          // B-load k within 32 (fid>>3, u adds 16)
    const int lnq = tid & 7;           // B-load n-quad

    float4 rA[4], rB[2];

    // prologue: load + stage chunk 0
#pragma unroll
    for (int u = 0; u < 4; u++)
        rA[u] = __ldcg(reinterpret_cast<const float4*>(A + (size_t)(m0 + lm + u * 16) * Hz + lkq * 4));
#pragma unroll
    for (int u = 0; u < 2; u++)
        rB[u] = __ldg(reinterpret_cast<const float4*>(Wt + (size_t)(lk + u * 16) * Hz + n0 + lnq * 4));
    {
        float* a = sA[0];
        float* b = sB[0];
#pragma unroll
        for (int u = 0; u < 4; u++) {
            int base = (lm + u * 16) * 33 + lkq * 4;
            a[base + 0] = rA[u].x; a[base + 1] = rA[u].y;
            a[base + 2] = rA[u].z; a[base + 3] = rA[u].w;
        }
#pragma unroll
        for (int u = 0; u < 2; u++)
            *reinterpret_cast<float4*>(b + (lk + u * 16) * 32 + lnq * 4) = rB[u];
    }
    __syncthreads();

#pragma unroll 1
    for (int c = 0; c < 16; c++) {
        const int kc_next = (c + 1) * 32;
        if (c < 15) {
#pragma unroll
            for (int u = 0; u < 4; u++)
                rA[u] = __ldcg(reinterpret_cast<const float4*>(A + (size_t)(m0 + lm + u * 16) * Hz + kc_next + lkq * 4));
#pragma unroll
            for (int u = 0; u < 2; u++)
                rB[u] = __ldg(reinterpret_cast<const float4*>(Wt + (size_t)(kc_next + lk + u * 16) * Hz + n0 + lnq * 4));
        }
        const float* a = sA[c & 1];
        const float* b = sB[c & 1];
#pragma unroll
        for (int kk = 0; kk < 32; kk++) {
            float a0 = a[(ty * 4 + 0) * 33 + kk];
            float a1 = a[(ty * 4 + 1) * 33 + kk];
            float a2 = a[(ty * 4 + 2) * 33 + kk];
            float a3 = a[(ty * 4 + 3) * 33 + kk];
            float4 bv = *reinterpret_cast<const float4*>(b + kk * 32 + tx * 4);
            acc[0][0] += a0 * bv.x; acc[0][1] += a0 * bv.y; acc[0][2] += a0 * bv.z; acc[0][3] += a0 * bv.w;
            acc[1][0] += a1 * bv.x; acc[1][1] += a1 * bv.y; acc[1][2] += a1 * bv.z; acc[1][3] += a1 * bv.w;
            acc[2][0] += a2 * bv.x; acc[2][1] += a2 * bv.y; acc[2][2] += a2 * bv.z; acc[2][3] += a2 * bv.w;
            acc[3][0] += a3 * bv.x; acc[3][1] += a3 * bv.y; acc[3][2] += a3 * bv.z; acc[3][3] += a3 * bv.w;
        }
        if (c < 15) {
            float* an = sA[(c + 1) & 1];
            float* bn = sB[(c + 1) & 1];
#pragma unroll
            for (int u = 0; u < 4; u++) {
                int base = (lm + u * 16) * 33 + lkq * 4;
                an[base + 0] = rA[u].x; an[base + 1] = rA[u].y;
                an[base + 2] = rA[u].z; an[base + 3] = rA[u].w;
            }
#pragma unroll
            for (int u = 0; u < 2; u++)
                *reinterpret_cast<float4*>(bn + (lk + u * 16) * 32 + lnq * 4) = rB[u];
            __syncthreads();
        }
    }
}

__device__ __forceinline__ void grid_barrier(unsigned expect) {
    __syncthreads();
    if (threadIdx.x == 0) {
        __threadfence();
        if (atomicAdd(&g_bar_arrive, 1) == NB - 1) {
            g_bar_arrive = 0;
            __threadfence();
            g_bar_gen = expect;
        } else {
            while ((int)(g_bar_gen - expect) < 0) { __nanosleep(32); }
            __threadfence();
        }
    }
    __syncthreads();
}

// ---------------- Phase B: persistent sequential scan ----------------
// Phase p (0..T): CTAs 0..63 compute layer0(t=p); CTAs 64..127 compute layer1(t=p-1).
// Parities: layer0 reads h0 at (p+1)&1, writes p&1.
//           layer1 reads h0 at (p+1)&1 and h1 at p&1, writes h1 at (p+1)&1.
__global__ void __launch_bounds__(NT, 1) k_seq(const float* __restrict__ bih1,
                                               const float* __restrict__ bhh1) {
    __shared__ float sA[2][64 * 33];
    __shared__ float sB[2][32 * 32];
    __shared__ unsigned sbase;
    const int tid = threadIdx.x, bid = blockIdx.x;
    if (tid == 0) sbase = g_bar_gen;
    __syncthreads();
    const unsigned base = sbase;

    const bool isL0 = (bid < 64);
    const int l  = isL0 ? bid : bid - 64;
    const int dir = l >> 5;
    const int m0 = ((l >> 4) & 1) * 64;
    const int n0 = (l & 15) * 32;
    const int ty = tid >> 3, tx = tid & 7;

    for (int p = 0; p <= Tz; p++) {
        const int qa = (p + 1) & 1;   // "previous step" parity
        const int qw = p & 1;
        if (isL0) {
            if (p < Tz) {
                float acc[4][4] = {};
                gemm512_acc(&g_h[qa][dir][0], g_WThh0 + (size_t)dir * Hz * Hz,
                            m0, n0, tid, sA, sB, acc);
                const float* p0 = g_P0 + (((size_t)p * 2 + dir) * Bz) * Hz;
                float* dst = &g_h[qw][dir][0];
#pragma unroll
                for (int i = 0; i < 4; i++) {
                    int row = m0 + ty * 4 + i;
                    float4 pv = __ldcg(reinterpret_cast<const float4*>(p0 + (size_t)row * Hz + n0 + tx * 4));
                    float4 o;
                    o.x = fmaxf(acc[i][0] + pv.x, 0.f);
                    o.y = fmaxf(acc[i][1] + pv.y, 0.f);
                    o.z = fmaxf(acc[i][2] + pv.z, 0.f);
                    o.w = fmaxf(acc[i][3] + pv.w, 0.f);
                    *reinterpret_cast<float4*>(dst + (size_t)row * Hz + n0 + tx * 4) = o;
                }
            }
        } else {
            if (p >= 1) {
                float acc[4][4] = {};
                const float* Aseg[3];
                const float* Wseg[3];
                Aseg[0] = &g_h[qa][0][0];
                Wseg[0] = g_WTih1 + (size_t)dir * H2z * Hz;
                Aseg[1] = &g_h[qa][1][0];
                Wseg[1] = g_WTih1 + (size_t)dir * H2z * Hz + (size_t)Hz * Hz;
                Aseg[2] = &g_h[qw][2 + dir][0];
                Wseg[2] = g_WThh1 + (size_t)dir * Hz * Hz;
#pragma unroll 1
                for (int s = 0; s < 3; s++)
                    gemm512_acc(Aseg[s], Wseg[s], m0, n0, tid, sA, sB, acc);

                float4 bi = __ldg(reinterpret_cast<const float4*>(bih1 + dir * Hz + n0 + tx * 4));
                float4 bh = __ldg(reinterpret_cast<const float4*>(bhh1 + dir * Hz + n0 + tx * 4));
                float* dst = &g_h[qa][2 + dir][0];
#pragma unroll
                for (int i = 0; i < 4; i++) {
                    int row = m0 + ty * 4 + i;
                    float4 o;
                    o.x = fmaxf(acc[i][0] + bi.x + bh.x, 0.f);
                    o.y = fmaxf(acc[i][1] + bi.y + bh.y, 0.f);
                    o.z = fmaxf(acc[i][2] + bi.z + bh.z, 0.f);
                    o.w = fmaxf(acc[i][3] + bi.w + bh.w, 0.f);
                    *reinterpret_cast<float4*>(dst + (size_t)row * Hz + n0 + tx * 4) = o;
                }
            }
        }
        grid_barrier(base + (unsigned)p + 1u);
    }
}

// ---------------- Head ----------------
__global__ void k_bn1(const float* __restrict__ g, const float* __restrict__ b) {
    __shared__ float s1[128], s2[128];
    int j = blockIdx.x, t = threadIdx.x;
    float v = (j < Hz) ? g_h[1][2][t * Hz + j] : g_h[1][3][t * Hz + j - Hz];
    s1[t] = v; s2[t] = v * v;
    __syncthreads();
    for (int o = 64; o > 0; o >>= 1) {
        if (t < o) { s1[t] += s1[t + o]; s2[t] += s2[t + o]; }
        __syncthreads();
    }
    float mean = s1[0] * (1.f / 128.f);
    float var  = s2[0] * (1.f / 128.f) - mean * mean;
    float y = (v - mean) * rsqrtf(var + EPSz) * __ldg(g + j) + __ldg(b + j);
    g_bn1[t * H2z + j] = fmaxf(y, 0.f);
}

// fc1: [128,2048] = g_bn1[128,1024] @ WTfc1 + fc1_b  (pre-BN, no relu)
__global__ void k_fc1(const float* __restrict__ bias) {
    __shared__ float sA[64 * 17];
    __shared__ float sB[16 * 64];
    const int tid = threadIdx.x;
    const int m0 = blockIdx.x * 64;
    const int n0 = blockIdx.y * 64;
    const int ty = tid >> 4, tx = tid & 15;
    float acc[4][4] = {};
    for (int kc = 0; kc < H2z; kc += 16) {
        __syncthreads();
        {
            int m = tid >> 2, kq = tid & 3;
            float4 v = *reinterpret_cast<const float4*>(g_bn1 + (size_t)(m0 + m) * H2z + kc + kq * 4);
            sA[m * 17 + kq * 4 + 0] = v.x;
            sA[m * 17 + kq * 4 + 1] = v.y;
            sA[m * 17 + kq * 4 + 2] = v.z;
            sA[m * 17 + kq * 4 + 3] = v.w;
        }
        {
            int k = tid >> 4, nq = tid & 15;
            float4 v = __ldg(reinterpret_cast<const float4*>(g_WTfc1 + (size_t)(kc + k) * H4z + n0 + nq * 4));
            *reinterpret_cast<float4*>(sB + k * 64 + nq * 4) = v;
        }
        __syncthreads();
#pragma unroll
        for (int kk = 0; kk < 16; kk++) {
            float a0 = sA[(ty * 4 + 0) * 17 + kk];
            float a1 = sA[(ty * 4 + 1) * 17 + kk];
            float a2 = sA[(ty * 4 + 2) * 17 + kk];
            float a3 = sA[(ty * 4 + 3) * 17 + kk];
            float4 b = *reinterpret_cast<float4*>(sB + kk * 64 + tx * 4);
            acc[0][0] += a0 * b.x; acc[0][1] += a0 * b.y; acc[0][2] += a0 * b.z; acc[0][3] += a0 * b.w;
            acc[1][0] += a1 * b.x; acc[1][1] += a1 * b.y; acc[1][2] += a1 * b.z; acc[1][3] += a1 * b.w;
            acc[2][0] += a2 * b.x; acc[2][1] += a2 * b.y; acc[2][2] += a2 * b.z; acc[2][3] += a2 * b.w;
            acc[3][0] += a3 * b.x; acc[3][1] += a3 * b.y; acc[3][2] += a3 * b.z; acc[3][3] += a3 * b.w;
        }
    }
    int n = n0 + tx * 4;
    float4 bi = __ldg(reinterpret_cast<const float4*>(bias + n));
#pragma unroll
    for (int i = 0; i < 4; i++) {
        int m = m0 + ty * 4 + i;
        float4 o;
        o.x = acc[i][0] + bi.x;
        o.y = acc[i][1] + bi.y;
        o.z = acc[i][2] + bi.z;
        o.w = acc[i][3] + bi.w;
        *reinterpret_cast<float4*>(g_fc1 + (size_t)m * H4z + n) = o;
    }
}

__global__ void k_bn2(const float* __restrict__ g, const float* __restrict__ b) {
    __shared__ float s1[128], s2[128];
    int j = blockIdx.x, t = threadIdx.x;
    float v = g_fc1[t * H4z + j];
    s1[t] = v; s2[t] = v * v;
    __syncthreads();
    for (int o = 64; o > 0; o >>= 1) {
        if (t < o) { s1[t] += s1[t + o]; s2[t] += s2[t + o]; }
        __syncthreads();
    }
    float mean = s1[0] * (1.f / 128.f);
    float var  = s2[0] * (1.f / 128.f) - mean * mean;
    float y = (v - mean) * rsqrtf(var + EPSz) * __ldg(g + j) + __ldg(b + j);
    g_bn2[t * H4z + j] = fmaxf(y, 0.f);
}

__global__ void k_fc2(const float* __restrict__ fb, float* __restrict__ out) {
    __shared__ float s[H4z];
    int b = blockIdx.x, t = threadIdx.x;
    for (int i = t; i < H4z; i += 128) s[i] = g_bn2[b * H4z + i];
    __syncthreads();
    float acc = __ldg(fb + t);
#pragma unroll 4
    for (int k = 0; k < H4z; k++) acc += s[k] * __ldg(&g_WTfc2[k * OUTz + t]);
    out[b * OUTz + t] = 1.f / (1.f + expf(-acc));
}

// ---------------- launcher ----------------
extern "C" void kernel_launch(void* const* d_in, const int* in_sizes, int n_in,
                              void* d_out, int out_size) {
    const float* x    = (const float*)d_in[0];
    const float* h0   = (const float*)d_in[1];
    const float* Wih0 = (const float*)d_in[2];
    const float* Whh0 = (const float*)d_in[3];
    const float* bih0 = (const float*)d_in[4];
    const float* bhh0 = (const float*)d_in[5];
    const float* Wih1 = (const float*)d_in[6];
    const float* Whh1 = (const float*)d_in[7];
    const float* bih1 = (const float*)d_in[8];
    const float* bhh1 = (const float*)d_in[9];
    const float* bn1g = (const float*)d_in[10];
    const float* bn1b = (const float*)d_in[11];
    const float* fc1W = (const float*)d_in[12];
    const float* fc1b = (const float*)d_in[13];
    const float* bn2g = (const float*)d_in[14];
    const float* bn2b = (const float*)d_in[15];
    const float* fc2W = (const float*)d_in[16];
    const float* fc2b = (const float*)d_in[17];
    float* out = (float*)d_out;

    float* dWTih0; cudaGetSymbolAddress((void**)&dWTih0, g_WTih0);
    float* dWThh0; cudaGetSymbolAddress((void**)&dWThh0, g_WThh0);
    float* dWTih1; cudaGetSymbolAddress((void**)&dWTih1, g_WTih1);
    float* dWThh1; cudaGetSymbolAddress((void**)&dWThh1, g_WThh1);
    float* dWTfc1; cudaGetSymbolAddress((void**)&dWTfc1, g_WTfc1);
    float* dWTfc2; cudaGetSymbolAddress((void**)&dWTfc2, g_WTfc2);

    auto tr = [&](const float* in, float* o, int D, int R, int C) {
        long total = (long)D * R * C;
        k_tr<<<(unsigned)((total + 255) / 256), 256>>>(in, o, D, R, C);
    };
    tr(Wih0, dWTih0, 2, Hz, INz);
    tr(Whh0, dWThh0, 2, Hz, Hz);
    tr(Wih1, dWTih1, 2, Hz, H2z);
    tr(Whh1, dWThh1, 2, Hz, Hz);
    tr(fc1W, dWTfc1, 1, H4z, H2z);
    tr(fc2W, dWTfc2, 1, OUTz, H4z);

    k_init_h<<<(4 * Bz * Hz + 255) / 256, 256>>>(h0);

    k_phase_a<<<dim3((Bz * Tz) / 64, Hz / 64, 2), 256>>>(x, bih0, bhh0);

    k_seq<<<NB, NT>>>(bih1, bhh1);

    k_bn1<<<H2z, 128>>>(bn1g, bn1b);
    k_fc1<<<dim3(Bz / 64, H4z / 64), 256>>>(fc1b);
    k_bn2<<<H4z, 128>>>(bn2g, bn2b);
    k_fc2<<<Bz, 128>>>(fc2b, out);
}